// round 1
// baseline (speedup 1.0000x reference)
#include <cuda_runtime.h>
#include <cstdint>

// ----------------------------------------------------------------------------
// RNG scheme selector (which jax.random bit-generation path the reference uses)
//   0 = legacy threefry (split counters / concat halves), jax_threefry_partitionable=False
//   1 = partitionable, 32-bit bits = out0 ^ out1          (modern JAX default)
//   2 = partitionable, 32-bit bits = out1 (low-word truncation)  [fallback hypothesis]
// ----------------------------------------------------------------------------
#ifndef RNG_SCHEME
#define RNG_SCHEME 1
#endif

#define KMIX 64
#define DDIM 16

__device__ float g_logp[KMIX];

// --- logp precompute: p = pi/sum(pi); logits = log(p) ------------------------
__global__ void prep_logp(const float* __restrict__ pi) {
    __shared__ float s_sum;
    int k = threadIdx.x;
    if (k == 0) {
        float acc = 0.0f;
        for (int j = 0; j < KMIX; j++) acc += pi[j];
        s_sum = acc;
    }
    __syncthreads();
    if (k < KMIX) g_logp[k] = logf(pi[k] / s_sum);
}

// --- threefry2x32, 20 rounds, key = jax.random.key(42) -> (0, 42) ------------
__device__ __forceinline__ uint2 threefry2x32(uint32_t x0, uint32_t x1) {
    const uint32_t ks0 = 0u;
    const uint32_t ks1 = 42u;
    const uint32_t ks2 = 0x1BD11BDAu ^ ks0 ^ ks1;
    x0 += ks0; x1 += ks1;
#define TF_R(r) { x0 += x1; x1 = __funnelshift_l(x1, x1, (r)); x1 ^= x0; }
    TF_R(13) TF_R(15) TF_R(26) TF_R(6)
    x0 += ks1; x1 += ks2 + 1u;
    TF_R(17) TF_R(29) TF_R(16) TF_R(24)
    x0 += ks2; x1 += ks0 + 2u;
    TF_R(13) TF_R(15) TF_R(26) TF_R(6)
    x0 += ks0; x1 += ks1 + 3u;
    TF_R(17) TF_R(29) TF_R(16) TF_R(24)
    x0 += ks1; x1 += ks2 + 4u;
    TF_R(13) TF_R(15) TF_R(26) TF_R(6)
    x0 += ks2; x1 += ks0 + 5u;
#undef TF_R
    return make_uint2(x0, x1);
}

// bits -> uniform in [tiny, 1), exactly as jax._src.random._uniform (f32)
__device__ __forceinline__ float bits_to_u(uint32_t b) {
    float u = __uint_as_float((b >> 9) | 0x3f800000u) - 1.0f;
    return (u == 0.0f) ? 1.17549435e-38f : u;
}

// fast gumbel with conservative error bound (error vs accurate logf path)
__device__ __forceinline__ float gumbel_fast(float u, float& err) {
    float t = -__logf(u);          // MUFU-based, abs err ~2^-21 for u in [0.5,1)
    float g = -__logf(t);
    // |err| <= a*max(1,|g|)  (outer log)  +  a*max(1,t)/t  (inner log propagated)
    err = 3e-6f * fmaxf(1.0f, fabsf(g)) + fmaxf(3e-6f, __fdividef(3e-6f, t));
    return g;
}

__device__ __forceinline__ float gumbel_exact(float u) {
    return -logf(-logf(u));        // accurate libdevice logf (matches XLA)
}

struct Top2 { float v1; int i1; float v2; float e; };

// warp top-2 (+ max error bound) reduction; tie -> smaller index (XLA argmax rule)
__device__ __forceinline__ Top2 warp_top2(float a0, float a1, int k0, int k1,
                                          float e0, float e1) {
    Top2 r;
    if (a0 >= a1) { r.v1 = a0; r.i1 = k0; r.v2 = a1; }
    else          { r.v1 = a1; r.i1 = k1; r.v2 = a0; }
    r.e = fmaxf(e0, e1);
#pragma unroll
    for (int o = 16; o; o >>= 1) {
        float ov1 = __shfl_xor_sync(0xffffffffu, r.v1, o);
        int   oi1 = __shfl_xor_sync(0xffffffffu, r.i1, o);
        float ov2 = __shfl_xor_sync(0xffffffffu, r.v2, o);
        float oe  = __shfl_xor_sync(0xffffffffu, r.e,  o);
        r.e = fmaxf(r.e, oe);
        if (ov1 > r.v1 || (ov1 == r.v1 && oi1 < r.i1)) {
            r.v2 = fmaxf(r.v1, ov2);
            r.v1 = ov1; r.i1 = oi1;
        } else {
            r.v2 = fmaxf(r.v2, ov1);
        }
    }
    return r;
}

__device__ __forceinline__ int warp_argmax(float a0, float a1, int k0, int k1) {
    float v; int i;
    if (a0 >= a1) { v = a0; i = k0; } else { v = a1; i = k1; }
#pragma unroll
    for (int o = 16; o; o >>= 1) {
        float ov = __shfl_xor_sync(0xffffffffu, v, o);
        int   oi = __shfl_xor_sync(0xffffffffu, i, o);
        if (ov > v || (ov == v && oi < i)) { v = ov; i = oi; }
    }
    return i;
}

// ----------------------------------------------------------------------------
// Main kernel: 1 warp handles 2 samples.
//   lane j owns components k = 2j, 2j+1 for both samples.
// ----------------------------------------------------------------------------
__global__ __launch_bounds__(256)
void gmm_sample_kernel(const float* __restrict__ x,
                       const float* __restrict__ means,
                       const float* __restrict__ Ls,
                       float* __restrict__ y,
                       int nPairs, int N) {
    __shared__ float s_logp[KMIX];
    if (threadIdx.x < KMIX) s_logp[threadIdx.x] = g_logp[threadIdx.x];
    __syncthreads();

    int warp = (blockIdx.x * blockDim.x + threadIdx.x) >> 5;
    int lane = threadIdx.x & 31;
    if (warp >= nPairs) return;

#if RNG_SCHEME == 0
    int half = N >> 1;
    int nA = warp;
    int nB = warp + half;
#else
    int nA = 2 * warp;
    int nB = 2 * warp + 1;
#endif

    int k0 = 2 * lane, k1 = 2 * lane + 1;
    float c0 = s_logp[k0], c1 = s_logp[k1];

    uint32_t bA0, bA1, bB0, bB1;
#if RNG_SCHEME == 0
    // legacy: counters 0..n-1 split in halves: block i has (x0=i, x1=i+n/2);
    // bits for sample nA come from out0, for sample nA+half from out1 (same k).
    uint32_t halfK = (uint32_t)half * (uint32_t)KMIX;
    uint32_t i0 = (uint32_t)nA * KMIX + (uint32_t)k0;
    uint32_t i1 = i0 + 1u;
    uint2 r0 = threefry2x32(i0, i0 + halfK);
    uint2 r1 = threefry2x32(i1, i1 + halfK);
    bA0 = r0.x; bA1 = r1.x; bB0 = r0.y; bB1 = r1.y;
#else
    // partitionable: per flat index i (< 2^32): threefry(key, hi=0, lo=i)
    uint32_t iA = (uint32_t)nA * KMIX + (uint32_t)k0;
    uint32_t iB = (uint32_t)nB * KMIX + (uint32_t)k0;
    uint2 rA0 = threefry2x32(0u, iA);
    uint2 rA1 = threefry2x32(0u, iA + 1u);
    uint2 rB0 = threefry2x32(0u, iB);
    uint2 rB1 = threefry2x32(0u, iB + 1u);
#if RNG_SCHEME == 1
    bA0 = rA0.x ^ rA0.y;  bA1 = rA1.x ^ rA1.y;
    bB0 = rB0.x ^ rB0.y;  bB1 = rB1.x ^ rB1.y;
#else
    bA0 = rA0.y;  bA1 = rA1.y;
    bB0 = rB0.y;  bB1 = rB1.y;
#endif
#endif

    float uA0 = bits_to_u(bA0), uA1 = bits_to_u(bA1);
    float uB0 = bits_to_u(bB0), uB1 = bits_to_u(bB1);

    // fast path: MUFU logs + error bounds
    float eA0, eA1, eB0, eB1;
    float vA0 = gumbel_fast(uA0, eA0) + c0;
    float vA1 = gumbel_fast(uA1, eA1) + c1;
    float vB0 = gumbel_fast(uB0, eB0) + c0;
    float vB1 = gumbel_fast(uB1, eB1) + c1;

    Top2 tA = warp_top2(vA0, vA1, k0, k1, eA0, eA1);
    Top2 tB = warp_top2(vB0, vB1, k0, k1, eB0, eB1);

    int zA = tA.i1;
    int zB = tB.i1;
    // warp-uniform slow path (rare): margin within error bound -> exact recompute
    if (tA.v1 - tA.v2 <= 2.0f * tA.e + 1e-6f)
        zA = warp_argmax(gumbel_exact(uA0) + c0, gumbel_exact(uA1) + c1, k0, k1);
    if (tB.v1 - tB.v2 <= 2.0f * tB.e + 1e-6f)
        zB = warp_argmax(gumbel_exact(uB0) + c0, gumbel_exact(uB1) + c1, k0, k1);

    // matvec: lanes 0..15 -> sample A outputs, lanes 16..31 -> sample B outputs
    int n = (lane < 16) ? nA : nB;
    int z = (lane < 16) ? zA : zB;
    int e = lane & 15;
    int src0 = lane & 16;

    float xv = x[(size_t)n * DDIM + e];           // lane d holds x[n, d]
    float acc = __ldg(&means[z * DDIM + e]);
    const float* Lb = Ls + (size_t)z * (DDIM * DDIM) + e;
#pragma unroll
    for (int d = 0; d < DDIM; d++) {
        float xd = __shfl_sync(0xffffffffu, xv, src0 + d);
        acc = fmaf(xd, __ldg(Lb + d * DDIM), acc);
    }
    y[(size_t)n * DDIM + e] = acc;
}

// ----------------------------------------------------------------------------
extern "C" void kernel_launch(void* const* d_in, const int* in_sizes, int n_in,
                              void* d_out, int out_size) {
    const float* x     = (const float*)d_in[0];   // (N, 16)
    const float* pi    = (const float*)d_in[1];   // (64,)
    const float* means = (const float*)d_in[2];   // (64, 16)
    const float* Ls    = (const float*)d_in[3];   // (64, 16, 16)
    float* y = (float*)d_out;                     // (N, 16)

    int N = in_sizes[0] / DDIM;
    int nPairs = N / 2;                           // N is even (1,000,000)

    prep_logp<<<1, 64>>>(pi);

    const int threads = 256;                      // 8 warps = 16 samples / CTA
    int warpsPerBlock = threads / 32;
    int blocks = (nPairs + warpsPerBlock - 1) / warpsPerBlock;
    gmm_sample_kernel<<<blocks, threads>>>(x, means, Ls, y, nPairs, N);
}

// round 2
// speedup vs baseline: 1.1852x; 1.1852x over previous
#include <cuda_runtime.h>
#include <cstdint>

#define KMIX 64
#define DDIM 16

__device__ float g_logp[KMIX];
__device__ float g_minlogp;

// --- logp precompute: p = pi/sum(pi); logits = log(p); also min logit --------
__global__ void prep_logp(const float* __restrict__ pi) {
    __shared__ float s_sum;
    int k = threadIdx.x;
    if (k == 0) {
        float acc = 0.0f;
        for (int j = 0; j < KMIX; j++) acc += pi[j];
        s_sum = acc;
    }
    __syncthreads();
    if (k < KMIX) {
        float lp = logf(pi[k] / s_sum);
        g_logp[k] = lp;
        if (k == 0) {
            float mn = 1e30f;
            for (int j = 0; j < KMIX; j++) mn = fminf(mn, logf(pi[j] / s_sum));
            g_minlogp = mn;
        }
    }
}

// rotate-left via widening multiply: IMAD.WIDE.U32 (fma pipe) instead of SHF (alu pipe)
__device__ __forceinline__ uint32_t mulrot(uint32_t v, int r) {
    uint64_t p = (uint64_t)v * (uint32_t)(1u << r);
    return (uint32_t)p | (uint32_t)(p >> 32);   // (lo|hi) fuses with ^x0 into LOP3
}

// --- threefry2x32, 20 rounds, key = jax.random.key(42) -> (0, 42) ------------
__device__ __forceinline__ uint2 threefry2x32(uint32_t x0, uint32_t x1) {
    const uint32_t ks0 = 0u;
    const uint32_t ks1 = 42u;
    const uint32_t ks2 = 0x1BD11BDAu ^ ks0 ^ ks1;
    x0 += ks0; x1 += ks1;
#define TF_R(r) { x0 += x1; x1 = (mulrot(x1, (r))) ^ x0; }
    TF_R(13) TF_R(15) TF_R(26) TF_R(6)
    x0 += ks1; x1 += ks2 + 1u;
    TF_R(17) TF_R(29) TF_R(16) TF_R(24)
    x0 += ks2; x1 += ks0 + 2u;
    TF_R(13) TF_R(15) TF_R(26) TF_R(6)
    x0 += ks0; x1 += ks1 + 3u;
    TF_R(17) TF_R(29) TF_R(16) TF_R(24)
    x0 += ks1; x1 += ks2 + 4u;
    TF_R(13) TF_R(15) TF_R(26) TF_R(6)
    x0 += ks2; x1 += ks0 + 5u;
#undef TF_R
    return make_uint2(x0, x1);
}

// partitionable-threefry random bits for flat index i: bits = out0 ^ out1
__device__ __forceinline__ uint32_t rng_bits(uint32_t i) {
    uint2 r = threefry2x32(0u, i);
    return r.x ^ r.y;
}

// bits -> uniform in [tiny, 1), exactly as jax._src.random._uniform (f32)
__device__ __forceinline__ float bits_to_u(uint32_t b) {
    float u = __uint_as_float((b >> 9) | 0x3f800000u) - 1.0f;
    return (u == 0.0f) ? 1.17549435e-38f : u;
}

__device__ __forceinline__ float gumbel_fast(float u) {
    return -__logf(-__logf(u));    // MUFU-based fast path
}
__device__ __forceinline__ float gumbel_exact(float u) {
    return -logf(-logf(u));        // accurate libdevice logf (matches XLA)
}

// ----------------------------------------------------------------------------
// Main kernel: 1 warp = 2 samples.
//   lanes 0..15  -> sample A, lane p owns components 4p..4p+3
//   lanes 16..31 -> sample B, lane 16+p owns components 4p..4p+3
// ----------------------------------------------------------------------------
__global__ __launch_bounds__(256)
void gmm_sample_kernel(const float* __restrict__ x,
                       const float* __restrict__ means,
                       const float* __restrict__ Ls,
                       float* __restrict__ y,
                       int nPairs) {
    __shared__ __align__(16) float s_logp[KMIX];
    if (threadIdx.x < KMIX) s_logp[threadIdx.x] = g_logp[threadIdx.x];
    __syncthreads();

    int warp = (blockIdx.x * blockDim.x + threadIdx.x) >> 5;
    int lane = threadIdx.x & 31;
    if (warp >= nPairs) return;

    int p = lane & 15;           // position within group
    int g = lane >> 4;           // 0 = sample A, 1 = sample B
    int n = 2 * warp + g;        // my sample index
    int kbase = 4 * p;           // first of my 4 components

    // 4 logits for my components: single 16B shared load
    float4 cv = *reinterpret_cast<const float4*>(&s_logp[kbase]);

    // 4 independent threefry hashes (flat index = n*64 + k)
    uint32_t ibase = (uint32_t)n * KMIX + (uint32_t)kbase;
    uint32_t b0 = rng_bits(ibase + 0u);
    uint32_t b1 = rng_bits(ibase + 1u);
    uint32_t b2 = rng_bits(ibase + 2u);
    uint32_t b3 = rng_bits(ibase + 3u);

    float u0 = bits_to_u(b0), u1 = bits_to_u(b1);
    float u2 = bits_to_u(b2), u3 = bits_to_u(b3);

    float v0 = gumbel_fast(u0) + cv.x;
    float v1 = gumbel_fast(u1) + cv.y;
    float v2 = gumbel_fast(u2) + cv.z;
    float v3 = gumbel_fast(u3) + cv.w;

    // local top-2 over 4 values (indices ascending -> ties keep lower index)
    float w1, w2; int j1;
    if (v0 >= v1) { w1 = v0; j1 = kbase;     w2 = v1; }
    else          { w1 = v1; j1 = kbase + 1; w2 = v0; }
    float t1, t2; int m1;
    if (v2 >= v3) { t1 = v2; m1 = kbase + 2; t2 = v3; }
    else          { t1 = v3; m1 = kbase + 3; t2 = v2; }
    if (t1 > w1) { w2 = fmaxf(w1, t2); w1 = t1; j1 = m1; }
    else         { w2 = fmaxf(w2, t1); }

    // 16-lane butterfly top-2 (both samples reduce in the same instructions)
#pragma unroll
    for (int o = 1; o < 16; o <<= 1) {
        float ov1 = __shfl_xor_sync(0xffffffffu, w1, o);
        int   oj1 = __shfl_xor_sync(0xffffffffu, j1, o);
        float ov2 = __shfl_xor_sync(0xffffffffu, w2, o);
        if (ov1 > w1 || (ov1 == w1 && oj1 < j1)) {
            w2 = fmaxf(w1, ov2); w1 = ov1; j1 = oj1;
        } else {
            w2 = fmaxf(w2, ov1);
        }
    }
    int z = j1;   // all 16 lanes of a group now agree

    // post-hoc error bound: fast-log error ~ 3e-6*(max(1,|g|) + e^g), g <= w1 - min(logp)
    float gmax = w1 - g_minlogp;
    float thr  = 6e-6f * (fmaxf(1.0f, fabsf(gmax)) + __expf(gmax)) + 1e-6f;
    bool  need = (w1 - w2) <= thr;

    if (__any_sync(0xffffffffu, need)) {   // rare slow path, warp-wide
        float e0 = gumbel_exact(u0) + cv.x;
        float e1 = gumbel_exact(u1) + cv.y;
        float e2 = gumbel_exact(u2) + cv.z;
        float e3 = gumbel_exact(u3) + cv.w;
        float av; int ai;
        if (e0 >= e1) { av = e0; ai = kbase; } else { av = e1; ai = kbase + 1; }
        if (e2 > av || (e2 == av && kbase + 2 < ai)) { av = e2; ai = kbase + 2; }
        if (e3 > av || (e3 == av && kbase + 3 < ai)) { av = e3; ai = kbase + 3; }
#pragma unroll
        for (int o = 1; o < 16; o <<= 1) {
            float ov = __shfl_xor_sync(0xffffffffu, av, o);
            int   oi = __shfl_xor_sync(0xffffffffu, ai, o);
            if (ov > av || (ov == av && oi < ai)) { av = ov; ai = oi; }
        }
        if (need) z = ai;
    }

    // matvec: lane (g,p) computes y[n][p] = dot(x[n,:], L[z][:,p]) + means[z][p]
    float xv = x[(size_t)n * DDIM + p];          // lane p holds x[n, p]
    float acc = __ldg(&means[z * DDIM + p]);
    const float* Lb = Ls + (size_t)z * (DDIM * DDIM) + p;
    int src0 = g << 4;
#pragma unroll
    for (int d = 0; d < DDIM; d++) {
        float xd = __shfl_sync(0xffffffffu, xv, src0 + d);
        acc = fmaf(xd, __ldg(Lb + d * DDIM), acc);
    }
    y[(size_t)n * DDIM + p] = acc;
}

// ----------------------------------------------------------------------------
extern "C" void kernel_launch(void* const* d_in, const int* in_sizes, int n_in,
                              void* d_out, int out_size) {
    const float* x     = (const float*)d_in[0];   // (N, 16)
    const float* pi    = (const float*)d_in[1];   // (64,)
    const float* means = (const float*)d_in[2];   // (64, 16)
    const float* Ls    = (const float*)d_in[3];   // (64, 16, 16)
    float* y = (float*)d_out;                     // (N, 16)

    int N = in_sizes[0] / DDIM;
    int nPairs = N / 2;                           // N = 1,000,000 (even)

    prep_logp<<<1, 64>>>(pi);

    const int threads = 256;                      // 8 warps = 16 samples / CTA
    int warpsPerBlock = threads / 32;
    int blocks = (nPairs + warpsPerBlock - 1) / warpsPerBlock;
    gmm_sample_kernel<<<blocks, threads>>>(x, means, Ls, y, nPairs);
}